// round 2
// baseline (speedup 1.0000x reference)
#include <cuda_runtime.h>
#include <math.h>

// MHFSpectralConv2D via pruned-DFT factorization.
// x[8,64,256,256] -> (w-DFT 17 modes) -> Aw -> (h-DFT 32 modes) -> Xf[512][544]
// -> (per-freq complex channel mix) -> Yf -> (inverse h-DFT) -> G ->
// (inverse w synthesis) -> out[8,64,256,256] + bias.
// Forward ortho 1/256 folded into K2; inverse 1/256 folded into the S table.

namespace {
constexpr int IMG = 512;                 // B*C = 8*64
constexpr int MX = 32, MY = 17, F = MX * MY;  // 544 live freqs
constexpr int NC = 34;                   // 17 re + 17 im columns
constexpr int NCP = 36;                  // padded to float4 multiple
}

// ---- persistent device scratch / tables (no runtime allocation) ----
__device__ float  g_Bw[256 * NCP];       // fwd w-basis  [w][36]: cos | -sin | 0,0
__device__ float2 g_Eh[256 * 32];        // [h][kx] = (cos, sin)(2*pi*kx*h/256)
__device__ float2 g_EhT[32 * 256];       // [kx][h] transposed copy
__device__ float  g_S[NCP * 256];        // inv synthesis [36][w], holds 1/256 & x2
__device__ float  g_Aw[(size_t)IMG * 256 * NC];   // [img][h][34]
__device__ float2 g_Xf[(size_t)IMG * F];          // [img][kx*17+ky]
__device__ float2 g_Yf[(size_t)IMG * F];          // [b*64+c_out][kx*17+ky]
__device__ float  g_G[(size_t)IMG * 256 * NCP];   // [img*256+h][36]

// ---------------------------------------------------------------------------
// K0: trig tables. Integer mod-256 reduction keeps sincospif arguments exact.
// ---------------------------------------------------------------------------
__global__ void k0_tables() {
    int tid = blockIdx.x * blockDim.x + threadIdx.x;
    int nt  = blockDim.x * gridDim.x;

    // g_Bw: [w][36]. cols 0..16: cos(2pi*ky*w/256); 17..33: -sin; 34,35: 0
    for (int idx = tid; idx < 256 * NCP; idx += nt) {
        int w = idx / NCP, c = idx % NCP;
        float v = 0.f;
        if (c < 17) {
            int m = (c * w) & 255; float s, co;
            sincospif((float)m * (1.f / 128.f), &s, &co);
            v = co;
        } else if (c < 34) {
            int ky = c - 17;
            int m = (ky * w) & 255; float s, co;
            sincospif((float)m * (1.f / 128.f), &s, &co);
            v = -s;
        }
        g_Bw[idx] = v;
    }

    // g_Eh / g_EhT: (cos, sin)(2*pi*kx*h/256)
    for (int idx = tid; idx < 256 * 32; idx += nt) {
        int h = idx >> 5, kx = idx & 31;
        int m = (kx * h) & 255; float s, co;
        sincospif((float)m * (1.f / 128.f), &s, &co);
        g_Eh[idx] = make_float2(co, s);
        g_EhT[kx * 256 + h] = make_float2(co, s);
    }

    // g_S: [36][w]. row0: 1/256; rows 1..16: 2cos/256; row17: 0;
    // rows 18..33: -2sin/256 (ky = row-17); rows 34,35: 0
    for (int idx = tid; idx < NCP * 256; idx += nt) {
        int k = idx >> 8, w = idx & 255;
        float v = 0.f;
        if (k == 0) {
            v = 1.f / 256.f;
        } else if (k < 17) {
            int m = (k * w) & 255; float s, co;
            sincospif((float)m * (1.f / 128.f), &s, &co);
            v = co * (2.f / 256.f);
        } else if (k >= 18 && k < 34) {
            int ky = k - 17;
            int m = (ky * w) & 255; float s, co;
            sincospif((float)m * (1.f / 128.f), &s, &co);
            v = -s * (2.f / 256.f);
        }
        g_S[idx] = v;
    }
}

// ---------------------------------------------------------------------------
// K1: forward w-DFT GEMM. Aw[row][0..33] = sum_w x[row][w] * Bw[w][col]
// row = img*256 + h, 131072 rows. Thread-per-row, 36 reg accumulators,
// basis rows read as float4 smem broadcasts (9 LDS.128 per 36 FFMA).
// ---------------------------------------------------------------------------
__global__ void __launch_bounds__(256) k1_wdft(const float* __restrict__ x) {
    __shared__ __align__(16) float Bsm[256 * NCP];
    for (int i = threadIdx.x; i < 256 * NCP; i += 256) Bsm[i] = g_Bw[i];
    __syncthreads();

    int row = blockIdx.x * 256 + threadIdx.x;
    const float4* xr = reinterpret_cast<const float4*>(x + (size_t)row * 256);

    float acc[NCP];
#pragma unroll
    for (int n = 0; n < NCP; n++) acc[n] = 0.f;

    for (int k4 = 0; k4 < 64; k4++) {
        float4 xv = xr[k4];
#pragma unroll
        for (int j = 0; j < 4; j++) {
            float xs = (j == 0) ? xv.x : (j == 1) ? xv.y : (j == 2) ? xv.z : xv.w;
            const float4* bp =
                reinterpret_cast<const float4*>(&Bsm[(k4 * 4 + j) * NCP]);
#pragma unroll
            for (int q = 0; q < 9; q++) {
                float4 b = bp[q];
                acc[q * 4 + 0] += xs * b.x;
                acc[q * 4 + 1] += xs * b.y;
                acc[q * 4 + 2] += xs * b.z;
                acc[q * 4 + 3] += xs * b.w;
            }
        }
    }
    float* o = g_Aw + (size_t)row * NC;
#pragma unroll
    for (int n = 0; n < NC; n++) o[n] = acc[n];
}

// ---------------------------------------------------------------------------
// K2: forward h-DFT, block per image. Xf[kx][ky] = (1/256) * sum_h
//   (Cr + i*Ci)(cos - i*sin),  psi = 2*pi*kx*h/256.
// 256 threads cover 544 (kx,ky) pairs (2-3 each). Aw + Eh tables in smem.
// ---------------------------------------------------------------------------
__global__ void __launch_bounds__(256) k2_hdft() {
    extern __shared__ float sm2[];
    float*  Aw = sm2;                                   // 256*34 floats
    float2* Eh = reinterpret_cast<float2*>(sm2 + 256 * NC);  // 256*32 float2

    int img = blockIdx.x;
    for (int i = threadIdx.x; i < 256 * NC; i += 256)
        Aw[i] = g_Aw[(size_t)img * 256 * NC + i];
    for (int i = threadIdx.x; i < 256 * 32; i += 256) Eh[i] = g_Eh[i];
    __syncthreads();

    int p0 = threadIdx.x, p1 = threadIdx.x + 256, p2 = threadIdx.x + 512;
    int kx0 = p0 / 17, ky0 = p0 % 17;
    int kx1 = p1 / 17, ky1 = p1 % 17;
    bool has2 = (p2 < F);                 // true exactly for warp 0 (uniform)
    int kx2 = has2 ? p2 / 17 : 0, ky2 = has2 ? p2 % 17 : 0;

    float xr0 = 0, xi0 = 0, xr1 = 0, xi1 = 0, xr2 = 0, xi2 = 0;
    for (int h = 0; h < 256; h++) {
        const float*  a = Aw + h * NC;
        const float2* e = Eh + h * 32;
        {
            float2 E = e[kx0]; float cr = a[ky0], ci = a[17 + ky0];
            xr0 += cr * E.x + ci * E.y;
            xi0 += ci * E.x - cr * E.y;
        }
        {
            float2 E = e[kx1]; float cr = a[ky1], ci = a[17 + ky1];
            xr1 += cr * E.x + ci * E.y;
            xi1 += ci * E.x - cr * E.y;
        }
        if (has2) {
            float2 E = e[kx2]; float cr = a[ky2], ci = a[17 + ky2];
            xr2 += cr * E.x + ci * E.y;
            xi2 += ci * E.x - cr * E.y;
        }
    }
    const float sc = 1.f / 256.f;
    g_Xf[(size_t)img * F + p0] = make_float2(xr0 * sc, xi0 * sc);
    g_Xf[(size_t)img * F + p1] = make_float2(xr1 * sc, xi1 * sc);
    if (has2) g_Xf[(size_t)img * F + p2] = make_float2(xr2 * sc, xi2 * sc);
}

// ---------------------------------------------------------------------------
// K3: per-frequency complex channel mix. Block per freq f.
// Yf[b][co] = sum_i Xf[b][i] * (Wr + i*Wi)[head(co)][i][o(co)][f]
// ---------------------------------------------------------------------------
__global__ void __launch_bounds__(128) k3_mix(const float* __restrict__ wr,
                                             const float* __restrict__ wi) {
    __shared__ float2 Xs[512];
    __shared__ float2 Ws[4096];   // [i][co]
    int f = blockIdx.x;

    for (int t = threadIdx.x; t < 512; t += 128)
        Xs[t] = g_Xf[(size_t)t * F + f];
    for (int t = threadIdx.x; t < 4096; t += 128) {
        int i = t >> 6, co = t & 63;
        int hd = co >> 4, o = co & 15;
        size_t a = (size_t)(((hd * 64 + i) * 16) + o) * F + f;
        Ws[t] = make_float2(wr[a], wi[a]);
    }
    __syncthreads();

#pragma unroll
    for (int u = 0; u < 4; u++) {
        int t2 = threadIdx.x + u * 128;
        int b = t2 >> 6, co = t2 & 63;
        float yr = 0.f, yi = 0.f;
#pragma unroll 8
        for (int i = 0; i < 64; i++) {
            float2 X = Xs[b * 64 + i];
            float2 W = Ws[i * 64 + co];
            yr += X.x * W.x - X.y * W.y;
            yi += X.x * W.y + X.y * W.x;
        }
        g_Yf[(size_t)(b * 64 + co) * F + f] = make_float2(yr, yi);
    }
}

// ---------------------------------------------------------------------------
// K4: inverse h-DFT (full complex ifft over kx, e^{+i}, unscaled here).
// Block per image, thread per h. G[h][ky] = sum_kx Yf[kx][ky] * e^{+i psi}.
// EhT transposed so per-thread (varying h) smem reads are conflict-free.
// ---------------------------------------------------------------------------
__global__ void __launch_bounds__(256) k4_ihdft() {
    extern __shared__ float sm4[];
    float2* EhT = reinterpret_cast<float2*>(sm4);      // 32*256
    float2* Ys  = EhT + 32 * 256;                      // 544

    int img = blockIdx.x;
    for (int i = threadIdx.x; i < 32 * 256; i += 256) EhT[i] = g_EhT[i];
    for (int i = threadIdx.x; i < F; i += 256)
        Ys[i] = g_Yf[(size_t)img * F + i];
    __syncthreads();

    int h = threadIdx.x;
    float gr[17], gi[17];
#pragma unroll
    for (int k = 0; k < 17; k++) { gr[k] = 0.f; gi[k] = 0.f; }

    for (int kx = 0; kx < 32; kx++) {
        float2 E = EhT[kx * 256 + h];
        const float2* y = Ys + kx * 17;
#pragma unroll
        for (int ky = 0; ky < 17; ky++) {
            float2 Y = y[ky];
            gr[ky] += Y.x * E.x - Y.y * E.y;
            gi[ky] += Y.x * E.y + Y.y * E.x;
        }
    }
    float* o = g_G + ((size_t)img * 256 + h) * NCP;
#pragma unroll
    for (int k = 0; k < 17; k++) { o[k] = gr[k]; o[17 + k] = gi[k]; }
    o[34] = 0.f; o[35] = 0.f;
}

// ---------------------------------------------------------------------------
// K5: inverse w synthesis GEMM. out[row][w] = bias + sum_k G[row][k]*S[k][w].
// Block = 16 rows (one image), thread per w: S column in 36 registers,
// G rows via float4 smem broadcasts. Coalesced output stores.
// ---------------------------------------------------------------------------
__global__ void __launch_bounds__(256) k5_synth(const float* __restrict__ bias,
                                               float* __restrict__ out) {
    __shared__ __align__(16) float Gs[16 * NCP];
    int r0 = blockIdx.x * 16;
    for (int i = threadIdx.x; i < 16 * NCP; i += 256)
        Gs[i] = g_G[(size_t)r0 * NCP + i];

    int w = threadIdx.x;
    float S[NCP];
#pragma unroll
    for (int k = 0; k < NCP; k++) S[k] = g_S[k * 256 + w];
    float bv = bias[(blockIdx.x >> 4) & 63];
    __syncthreads();

#pragma unroll 4
    for (int r = 0; r < 16; r++) {
        float acc = bv;
        const float4* gp = reinterpret_cast<const float4*>(&Gs[r * NCP]);
#pragma unroll
        for (int q = 0; q < 9; q++) {
            float4 g = gp[q];
            acc += g.x * S[q * 4 + 0] + g.y * S[q * 4 + 1] +
                   g.z * S[q * 4 + 2] + g.w * S[q * 4 + 3];
        }
        out[((size_t)(r0 + r)) * 256 + w] = acc;
    }
}

// ---------------------------------------------------------------------------
extern "C" void kernel_launch(void* const* d_in, const int* in_sizes, int n_in,
                              void* d_out, int out_size) {
    const float* x    = (const float*)d_in[0];
    const float* wr   = (const float*)d_in[1];
    const float* wi   = (const float*)d_in[2];
    const float* bias = (const float*)d_in[3];
    float* out = (float*)d_out;

    const int K2_SMEM = 256 * NC * 4 + 256 * 32 * 8;   // 100352 B
    const int K4_SMEM = 32 * 256 * 8 + F * 8;          // 69888 B
    cudaFuncSetAttribute(k2_hdft, cudaFuncAttributeMaxDynamicSharedMemorySize,
                         K2_SMEM);
    cudaFuncSetAttribute(k4_ihdft, cudaFuncAttributeMaxDynamicSharedMemorySize,
                         K4_SMEM);

    k0_tables<<<64, 256>>>();
    k1_wdft<<<512, 256>>>(x);
    k2_hdft<<<IMG, 256, K2_SMEM>>>();
    k3_mix<<<F, 128>>>(wr, wi);
    k4_ihdft<<<IMG, 256, K4_SMEM>>>();
    k5_synth<<<8192, 256>>>(bias, out);
}

// round 3
// speedup vs baseline: 1.1035x; 1.1035x over previous
#include <cuda_runtime.h>
#include <math.h>

// MHFSpectralConv2D via pruned-DFT factorization, round 3.
// x[8,64,256,256] -> (sym-folded w-DFT, 17 modes) -> Aw -> (h-DFT 32 modes)
// -> XfT[f][img] -> (per-freq complex mix, transposed weights) -> YfT[f][img]
// -> (inverse h-DFT) -> G -> (sym-folded inverse w synthesis, f32x2) -> out.

namespace {
constexpr int IMG = 512;                      // B*C = 8*64
constexpr int MX = 32, MY = 17, F = MX * MY;  // 544 live freqs
constexpr int NC = 34;                        // 17 re + 17 im columns (Aw)
constexpr int NCG = 36;                       // G row stride
}

// ---- persistent device scratch / tables (no runtime allocation) ----
__device__ float  g_TK1[129 * 36];            // K1 folded basis [w][36]
__device__ float2 g_Eh[256 * 32];             // [h][kx] = (cos, sin)
__device__ float2 g_EhT[32 * 256];            // [kx][h]
__device__ float2 g_PC5[17 * 128];            // K5 cos coef, duplicated lanes
__device__ float2 g_PS5[17 * 128];            // K5 sin coef, duplicated lanes
__device__ float  g_Aw[(size_t)IMG * 256 * NC];
__device__ float2 g_XfT[(size_t)F * IMG];     // [f][img]
__device__ float2 g_WT[(size_t)F * 4096];     // [f][i*64+co]
__device__ float2 g_YfT[(size_t)F * IMG];     // [f][img]
__device__ float  g_G[(size_t)IMG * 256 * NCG];

// ---- f32x2 helpers ----
__device__ __forceinline__ unsigned long long ffma2(unsigned long long a,
                                                    unsigned long long b,
                                                    unsigned long long c) {
    unsigned long long d;
    asm("fma.rn.f32x2 %0, %1, %2, %3;" : "=l"(d) : "l"(a), "l"(b), "l"(c));
    return d;
}
__device__ __forceinline__ float2 upk(unsigned long long v) {
    float2 r;
    asm("mov.b64 {%0,%1}, %2;" : "=f"(r.x), "=f"(r.y) : "l"(v));
    return r;
}

// ---------------------------------------------------------------------------
// K0: trig tables. Integer mod-256 reduction keeps sincospif arguments exact.
// ---------------------------------------------------------------------------
__global__ void k0_tables() {
    int tid = blockIdx.x * blockDim.x + threadIdx.x;
    int nt  = blockDim.x * gridDim.x;

    // g_TK1: [w 0..128][36]. cols 0..16: cos(2pi*ky*w/256); 17..33: -sin; pad
    for (int idx = tid; idx < 129 * 36; idx += nt) {
        int w = idx / 36, j = idx % 36;
        float v = 0.f;
        if (j < 17) {
            int m = (j * w) & 255; float s, co;
            sincospif((float)m * (1.f / 128.f), &s, &co);
            v = co;
        } else if (j < 34) {
            int ky = j - 17;
            int m = (ky * w) & 255; float s, co;
            sincospif((float)m * (1.f / 128.f), &s, &co);
            v = -s;
        }
        g_TK1[idx] = v;
    }

    // g_Eh / g_EhT: (cos, sin)(2*pi*kx*h/256)
    for (int idx = tid; idx < 256 * 32; idx += nt) {
        int h = idx >> 5, kx = idx & 31;
        int m = (kx * h) & 255; float s, co;
        sincospif((float)m * (1.f / 128.f), &s, &co);
        g_Eh[idx] = make_float2(co, s);
        g_EhT[kx * 256 + h] = make_float2(co, s);
    }

    // K5 coefficient tables [k][w], both float2 lanes identical.
    // ce: k==0 -> 1/256 ; else 2*cos(2pi*k*w/256)/256
    // cs: -2*sin(2pi*k*w/256)/256
    for (int idx = tid; idx < 17 * 128; idx += nt) {
        int k = idx >> 7, w = idx & 127;
        int m = (k * w) & 255; float s, co;
        sincospif((float)m * (1.f / 128.f), &s, &co);
        float ce = (k == 0) ? (1.f / 256.f) : co * (2.f / 256.f);
        float cs = -s * (2.f / 256.f);
        g_PC5[idx] = make_float2(ce, ce);
        g_PS5[idx] = make_float2(cs, cs);
    }
}

// ---------------------------------------------------------------------------
// K1: symmetry-folded forward w-DFT. Thread per row (= img*256 + h).
// u[w]=x[w]+x[256-w], v[w]=x[w]-x[256-w]; loop w=1..128 with edge
// compensation (w=128 double-counted in u; x[0] term added in epilogue).
// re[ky] = sum u*cos + (x0 - x128*(-1)^ky); im[ky] = sum v*(-sin).
// ---------------------------------------------------------------------------
__global__ void __launch_bounds__(256) k1_wdft(const float* __restrict__ x) {
    __shared__ __align__(16) float TK[129 * 36];
    for (int i = threadIdx.x; i < 129 * 36; i += 256) TK[i] = g_TK1[i];
    __syncthreads();

    int row = blockIdx.x * 256 + threadIdx.x;
    const float4* xr = reinterpret_cast<const float4*>(x + (size_t)row * 256);

    float acc[34];
#pragma unroll
    for (int j = 0; j < 34; j++) acc[j] = 0.f;

    float4 prev = xr[0];
    float x0 = prev.x;

#pragma unroll 2
    for (int k = 0; k < 32; k++) {
        float4 cur = xr[k + 1];
        float4 bk  = xr[63 - k];
        float fr[4]  = {prev.y, prev.z, prev.w, cur.x};
        float bkr[4] = {bk.w, bk.z, bk.y, bk.x};
#pragma unroll
        for (int j = 0; j < 4; j++) {
            int w = 4 * k + 1 + j;
            float u = fr[j] + bkr[j];
            float v = fr[j] - bkr[j];
            const float4* t4 = reinterpret_cast<const float4*>(&TK[w * 36]);
#pragma unroll
            for (int q = 0; q < 9; q++) {
                float4 tv = t4[q];
                int j0 = q * 4;
                if (j0 + 0 < 34) acc[j0 + 0] += ((j0 + 0) < 17 ? u : v) * tv.x;
                if (j0 + 1 < 34) acc[j0 + 1] += ((j0 + 1) < 17 ? u : v) * tv.y;
                if (j0 + 2 < 34) acc[j0 + 2] += ((j0 + 2) < 17 ? u : v) * tv.z;
                if (j0 + 3 < 34) acc[j0 + 3] += ((j0 + 3) < 17 ? u : v) * tv.w;
            }
        }
        prev = cur;
    }

    // epilogue: + x0 - x128*(-1)^ky on the real parts
    float x128 = prev.x;              // prev == xr[32]
    float ea = x0 - x128, eb = x0 + x128;
#pragma unroll
    for (int j = 0; j < 17; j++) acc[j] += (j & 1) ? eb : ea;

    float* o = g_Aw + (size_t)row * NC;
#pragma unroll
    for (int j = 0; j < 17; j++)
        *reinterpret_cast<float2*>(o + 2 * j) = make_float2(acc[2 * j], acc[2 * j + 1]);
}

// ---------------------------------------------------------------------------
// K2: forward h-DFT, block per image. Writes transposed XfT[f][img].
// ---------------------------------------------------------------------------
__global__ void __launch_bounds__(256) k2_hdft() {
    extern __shared__ float sm2[];
    float*  Aw = sm2;                                        // 256*34
    float2* Eh = reinterpret_cast<float2*>(sm2 + 256 * NC);  // 256*32

    int img = blockIdx.x;
    for (int i = threadIdx.x; i < 256 * NC; i += 256)
        Aw[i] = g_Aw[(size_t)img * 256 * NC + i];
    for (int i = threadIdx.x; i < 256 * 32; i += 256) Eh[i] = g_Eh[i];
    __syncthreads();

    int p0 = threadIdx.x, p1 = threadIdx.x + 256, p2 = threadIdx.x + 512;
    int kx0 = p0 / 17, ky0 = p0 % 17;
    int kx1 = p1 / 17, ky1 = p1 % 17;
    bool has2 = (p2 < F);
    int kx2 = has2 ? p2 / 17 : 0, ky2 = has2 ? p2 % 17 : 0;

    float xr0 = 0, xi0 = 0, xr1 = 0, xi1 = 0, xr2 = 0, xi2 = 0;
    for (int h = 0; h < 256; h++) {
        const float*  a = Aw + h * NC;
        const float2* e = Eh + h * 32;
        {
            float2 E = e[kx0]; float cr = a[ky0], ci = a[17 + ky0];
            xr0 += cr * E.x + ci * E.y;
            xi0 += ci * E.x - cr * E.y;
        }
        {
            float2 E = e[kx1]; float cr = a[ky1], ci = a[17 + ky1];
            xr1 += cr * E.x + ci * E.y;
            xi1 += ci * E.x - cr * E.y;
        }
        if (has2) {
            float2 E = e[kx2]; float cr = a[ky2], ci = a[17 + ky2];
            xr2 += cr * E.x + ci * E.y;
            xi2 += ci * E.x - cr * E.y;
        }
    }
    const float sc = 1.f / 256.f;
    g_XfT[(size_t)p0 * IMG + img] = make_float2(xr0 * sc, xi0 * sc);
    g_XfT[(size_t)p1 * IMG + img] = make_float2(xr1 * sc, xi1 * sc);
    if (has2) g_XfT[(size_t)p2 * IMG + img] = make_float2(xr2 * sc, xi2 * sc);
}

// ---------------------------------------------------------------------------
// K2b: weight transpose -> WT[f][i*64 + co] with co = hd*16 + o.
// Tiled: block = (input channel i, f-tile of 16). Coalesced in and out.
// ---------------------------------------------------------------------------
__global__ void __launch_bounds__(256) k2b_wt(const float* __restrict__ wr,
                                             const float* __restrict__ wi) {
    __shared__ float2 sm[16 * 65];
    int i  = blockIdx.x / 34;
    int f0 = (blockIdx.x % 34) * 16;

    for (int idx = threadIdx.x; idx < 1024; idx += 256) {
        int hdo = idx >> 4, fo = idx & 15;
        int hd = hdo >> 4, o = hdo & 15;
        size_t src = (size_t)(((hd * 64 + i) * 16) + o) * F + f0 + fo;
        sm[fo * 65 + hdo] = make_float2(wr[src], wi[src]);
    }
    __syncthreads();
    for (int idx = threadIdx.x; idx < 1024; idx += 256) {
        int fo = idx >> 6, j = idx & 63;
        g_WT[(size_t)(f0 + fo) * 4096 + i * 64 + j] = sm[fo * 65 + j];
    }
}

// ---------------------------------------------------------------------------
// K3: per-frequency complex channel mix, fully coalesced layouts.
// ---------------------------------------------------------------------------
__global__ void __launch_bounds__(128) k3_mix() {
    __shared__ __align__(16) float2 Xs[512];
    __shared__ __align__(16) float2 Ws[4096];   // [i][co]
    int f = blockIdx.x;

    const float4* wsrc = reinterpret_cast<const float4*>(g_WT + (size_t)f * 4096);
    float4* wd = reinterpret_cast<float4*>(Ws);
    for (int t = threadIdx.x; t < 2048; t += 128) wd[t] = wsrc[t];
    const float4* xsrc = reinterpret_cast<const float4*>(g_XfT + (size_t)f * IMG);
    float4* xd = reinterpret_cast<float4*>(Xs);
    for (int t = threadIdx.x; t < 256; t += 128) xd[t] = xsrc[t];
    __syncthreads();

#pragma unroll
    for (int u = 0; u < 4; u++) {
        int t2 = threadIdx.x + u * 128;
        int b = t2 >> 6, co = t2 & 63;
        float yr = 0.f, yi = 0.f;
#pragma unroll 8
        for (int i = 0; i < 64; i++) {
            float2 X = Xs[b * 64 + i];
            float2 W = Ws[i * 64 + co];
            yr += X.x * W.x - X.y * W.y;
            yi += X.x * W.y + X.y * W.x;
        }
        g_YfT[(size_t)f * IMG + t2] = make_float2(yr, yi);
    }
}

// ---------------------------------------------------------------------------
// K4: inverse h-DFT. Block per output image, thread per h.
// ---------------------------------------------------------------------------
__global__ void __launch_bounds__(256) k4_ihdft() {
    extern __shared__ float sm4[];
    float2* EhT = reinterpret_cast<float2*>(sm4);   // 32*256
    float2* Ys  = EhT + 32 * 256;                   // 544

    int img = blockIdx.x;
    for (int i = threadIdx.x; i < 32 * 256; i += 256) EhT[i] = g_EhT[i];
    for (int i = threadIdx.x; i < F; i += 256)
        Ys[i] = g_YfT[(size_t)i * IMG + img];
    __syncthreads();

    int h = threadIdx.x;
    float gr[17], gi[17];
#pragma unroll
    for (int k = 0; k < 17; k++) { gr[k] = 0.f; gi[k] = 0.f; }

    for (int kx = 0; kx < 32; kx++) {
        float2 E = EhT[kx * 256 + h];
        const float2* y = Ys + kx * 17;
#pragma unroll
        for (int ky = 0; ky < 17; ky++) {
            float2 Y = y[ky];
            gr[ky] += Y.x * E.x - Y.y * E.y;
            gi[ky] += Y.x * E.y + Y.y * E.x;
        }
    }
    float* o = g_G + ((size_t)img * 256 + h) * NCG;
#pragma unroll
    for (int k = 0; k < 17; k++) { o[k] = gr[k]; o[17 + k] = gi[k]; }
    o[34] = 0.f; o[35] = 0.f;
}

// ---------------------------------------------------------------------------
// K5: symmetry-folded inverse w synthesis with packed f32x2 over row pairs.
// Block = 16 rows (one image slice). Thread (w, half): w in 0..127.
// E[w] = sum_ky Gr[ky]*ce, O[w] = sum_ky Gi[ky]*cs;
// out[w] = E+O+bias, out[256-w] = E-O+bias; w==0 thread also emits col 128.
// f32x2 lanes carry two adjacent rows.
// ---------------------------------------------------------------------------
__global__ void __launch_bounds__(256) k5_synth(const float* __restrict__ bias,
                                               float* __restrict__ out) {
    __shared__ __align__(16) float2 Gs[34 * 8];   // [k][pair]
    int r0 = blockIdx.x * 16;
    for (int idx = threadIdx.x; idx < 34 * 8; idx += 256) {
        int k = idx >> 3, p = idx & 7;
        Gs[idx] = make_float2(g_G[(size_t)(r0 + 2 * p)     * NCG + k],
                              g_G[(size_t)(r0 + 2 * p + 1) * NCG + k]);
    }
    int w = threadIdx.x & 127;
    int half = threadIdx.x >> 7;

    unsigned long long ce[17], cs[17];
    const unsigned long long* PC = reinterpret_cast<const unsigned long long*>(g_PC5);
    const unsigned long long* PS = reinterpret_cast<const unsigned long long*>(g_PS5);
#pragma unroll
    for (int k = 0; k < 17; k++) {
        ce[k] = PC[k * 128 + w];
        cs[k] = PS[k * 128 + w];
    }
    float bv = bias[(blockIdx.x >> 4) & 63];
    __syncthreads();

#pragma unroll
    for (int g = 0; g < 2; g++) {
        int pa = half * 4 + g * 2;               // pairs pa, pa+1 -> rows 2pa..2pa+3
        unsigned long long Ea = 0, Eb = 0, Oa = 0, Ob = 0;
#pragma unroll
        for (int k = 0; k < 17; k++) {
            ulonglong2 q = *reinterpret_cast<const ulonglong2*>(&Gs[k * 8 + pa]);
            Ea = ffma2(q.x, ce[k], Ea);
            Eb = ffma2(q.y, ce[k], Eb);
        }
#pragma unroll
        for (int k = 1; k < 17; k++) {
            ulonglong2 q = *reinterpret_cast<const ulonglong2*>(&Gs[(17 + k) * 8 + pa]);
            Oa = ffma2(q.x, cs[k], Oa);
            Ob = ffma2(q.y, cs[k], Ob);
        }
        float2 e0 = upk(Ea), e1 = upk(Eb), o0 = upk(Oa), o1 = upk(Ob);
        size_t ra = (size_t)(r0 + 2 * pa) * 256;
        out[ra           + w] = e0.x + o0.x + bv;
        out[ra + 256     + w] = e0.y + o0.y + bv;
        out[ra + 512     + w] = e1.x + o1.x + bv;
        out[ra + 768     + w] = e1.y + o1.y + bv;
        if (w) {
            int wm = 256 - w;
            out[ra        + wm] = e0.x - o0.x + bv;
            out[ra + 256  + wm] = e0.y - o0.y + bv;
            out[ra + 512  + wm] = e1.x - o1.x + bv;
            out[ra + 768  + wm] = e1.y - o1.y + bv;
        } else {
            // Nyquist-equivalent column 128: cos = (-1)^ky, sin = 0
            unsigned long long E8a = 0, E8b = 0;
#pragma unroll
            for (int k = 0; k < 17; k++) {
                ulonglong2 q = *reinterpret_cast<const ulonglong2*>(&Gs[k * 8 + pa]);
                float m = (k == 0) ? (1.f / 256.f)
                                   : ((k & 1) ? (-2.f / 256.f) : (2.f / 256.f));
                unsigned long long m2;
                asm("mov.b64 %0, {%1,%1};" : "=l"(m2) : "f"(m));
                E8a = ffma2(q.x, m2, E8a);
                E8b = ffma2(q.y, m2, E8b);
            }
            float2 a8 = upk(E8a), b8 = upk(E8b);
            out[ra          + 128] = a8.x + bv;
            out[ra + 256    + 128] = a8.y + bv;
            out[ra + 512    + 128] = b8.x + bv;
            out[ra + 768    + 128] = b8.y + bv;
        }
    }
}

// ---------------------------------------------------------------------------
extern "C" void kernel_launch(void* const* d_in, const int* in_sizes, int n_in,
                              void* d_out, int out_size) {
    const float* x    = (const float*)d_in[0];
    const float* wr   = (const float*)d_in[1];
    const float* wi   = (const float*)d_in[2];
    const float* bias = (const float*)d_in[3];
    float* out = (float*)d_out;

    const int K2_SMEM = 256 * NC * 4 + 256 * 32 * 8;   // 100352 B
    const int K4_SMEM = 32 * 256 * 8 + F * 8;          // 69888 B
    cudaFuncSetAttribute(k2_hdft, cudaFuncAttributeMaxDynamicSharedMemorySize,
                         K2_SMEM);
    cudaFuncSetAttribute(k4_ihdft, cudaFuncAttributeMaxDynamicSharedMemorySize,
                         K4_SMEM);

    k0_tables<<<64, 256>>>();
    k1_wdft<<<512, 256>>>(x);
    k2_hdft<<<IMG, 256, K2_SMEM>>>();
    k2b_wt<<<64 * 34, 256>>>(wr, wi);
    k3_mix<<<F, 128>>>();
    k4_ihdft<<<IMG, 256, K4_SMEM>>>();
    k5_synth<<<8192, 256>>>(bias, out);
}

// round 4
// speedup vs baseline: 1.5959x; 1.4463x over previous
#include <cuda_runtime.h>
#include <math.h>

// MHFSpectralConv2D via pruned-DFT factorization, round 4.
// K1 (staged folded w-DFT GEMM) -> Aw[img][h][36] -> K2 (h-DFT, broadcast
// rows, f32x2) -> XfT[f][img] -> k2b/K3 (transposed mix) -> YfT[f][img] ->
// K45 (fused inverse h-DFT -> smem -> folded f32x2 w-synthesis) -> out.

namespace {
constexpr int IMG = 512;                      // B*C = 8*64
constexpr int MX = 32, MY = 17, F = MX * MY;  // 544 live freqs
constexpr int NCA = 36;                       // Aw row: re 0..17, im 18..35
}

// ---- persistent device scratch / tables ----
__device__ float  g_TK1[129 * 36];   // [w][36]: cos ky 0..16 | 0 | -sin ky 0..16 | 0
__device__ float2 g_Eh[256 * 32];    // [h][kx] = (cos, sin)
__device__ float2 g_EhT[32 * 256];   // [kx][h]
__device__ float2 g_PC5[17 * 128];   // K5 cos coef, duplicated lanes
__device__ float2 g_PS5[17 * 128];   // K5 sin coef, duplicated lanes
__device__ float  g_Aw[(size_t)IMG * 256 * NCA];
__device__ float2 g_XfT[(size_t)F * IMG];     // [f][img]
__device__ float2 g_WT[(size_t)F * 4096];     // [f][i*64+co]
__device__ float2 g_YfT[(size_t)F * IMG];     // [f][img]

// ---- f32x2 helpers ----
typedef unsigned long long u64;
__device__ __forceinline__ u64 ffma2(u64 a, u64 b, u64 c) {
    u64 d;
    asm("fma.rn.f32x2 %0, %1, %2, %3;" : "=l"(d) : "l"(a), "l"(b), "l"(c));
    return d;
}
__device__ __forceinline__ float2 upk(u64 v) {
    float2 r;
    asm("mov.b64 {%0,%1}, %2;" : "=f"(r.x), "=f"(r.y) : "l"(v));
    return r;
}
__device__ __forceinline__ u64 pk(float a, float b) {
    u64 v;
    asm("mov.b64 %0, {%1,%2};" : "=l"(v) : "f"(a), "f"(b));
    return v;
}

// ---------------------------------------------------------------------------
// K0: trig tables (exact integer mod-256 reduction).
// ---------------------------------------------------------------------------
__global__ void k0_tables() {
    int tid = blockIdx.x * blockDim.x + threadIdx.x;
    int nt  = blockDim.x * gridDim.x;

    // g_TK1: [w 0..128][36]. c<17: cos(2pi*c*w/256); c==17: 0;
    // 18<=c<35: -sin(2pi*(c-18)*w/256); c==35: 0.
    for (int idx = tid; idx < 129 * 36; idx += nt) {
        int w = idx / 36, c = idx % 36;
        float v = 0.f;
        if (c < 17) {
            int m = (c * w) & 255; float s, co;
            sincospif((float)m * (1.f / 128.f), &s, &co);
            v = co;
        } else if (c >= 18 && c < 35) {
            int ky = c - 18;
            int m = (ky * w) & 255; float s, co;
            sincospif((float)m * (1.f / 128.f), &s, &co);
            v = -s;
        }
        g_TK1[idx] = v;
    }

    for (int idx = tid; idx < 256 * 32; idx += nt) {
        int h = idx >> 5, kx = idx & 31;
        int m = (kx * h) & 255; float s, co;
        sincospif((float)m * (1.f / 128.f), &s, &co);
        g_Eh[idx] = make_float2(co, s);
        g_EhT[kx * 256 + h] = make_float2(co, s);
    }

    for (int idx = tid; idx < 17 * 128; idx += nt) {
        int k = idx >> 7, w = idx & 127;
        int m = (k * w) & 255; float s, co;
        sincospif((float)m * (1.f / 128.f), &s, &co);
        float ce = (k == 0) ? (1.f / 256.f) : co * (2.f / 256.f);
        float cs = -s * (2.f / 256.f);
        g_PC5[idx] = make_float2(ce, ce);
        g_PS5[idx] = make_float2(cs, cs);
    }
}

// ---------------------------------------------------------------------------
// K1: staged, folded forward w-DFT. Block = 64 rows, 256 threads.
// Thread (r = t>>2, p = t&3) handles w = 4j+p+1, j=0..31.
// x staged at row-stride 260 -> both fold reads conflict-free
// (banks (4r + p + ...) and (4r - p + ...) each cover all 32).
// acc: 18 f32x2 pairs; pairs 0..8 scaled by {u,u}, 9..17 by {v,v}.
// Epilogue (x0, x128) on p==0. 4-way reduction at smem stride 37.
// ---------------------------------------------------------------------------
__global__ void __launch_bounds__(256) k1_wdft(const float* __restrict__ x) {
    extern __shared__ __align__(16) float sm1[];
    float* TK = sm1;             // 129*36 = 4644 floats
    float* Xs = sm1 + 4656;      // 64*260 = 16640 floats (union w/ red)

    for (int i = threadIdx.x; i < 129 * 36; i += 256) TK[i] = g_TK1[i];

    // stage 64 rows of x, coalesced
    const float4* xg = reinterpret_cast<const float4*>(
        x + (size_t)blockIdx.x * 64 * 256);
#pragma unroll
    for (int k = 0; k < 16; k++) {
        int fidx = k * 256 + threadIdx.x;
        int row = fidx >> 6, c4 = fidx & 63;
        float4 v = xg[fidx];
        float* d = Xs + row * 260 + c4 * 4;
        d[0] = v.x; d[1] = v.y; d[2] = v.z; d[3] = v.w;
    }
    __syncthreads();

    int r = threadIdx.x >> 2, p = threadIdx.x & 3;
    const float* xrow = Xs + r * 260;

    u64 acc[18];
#pragma unroll
    for (int q = 0; q < 18; q++) acc[q] = 0;

#pragma unroll 4
    for (int j = 0; j < 32; j++) {
        int w = 4 * j + p + 1;
        float a = xrow[w];
        float b = xrow[256 - w];
        u64 uu = pk(a + b, a + b);
        u64 vv = pk(a - b, a - b);
        const ulonglong2* t2 = reinterpret_cast<const ulonglong2*>(TK + w * 36);
#pragma unroll
        for (int q = 0; q < 9; q++) {
            ulonglong2 tv = t2[q];
            if (q < 5) {   // pairs 0..8 from first 4.5 vec loads: handle evenly
            }
            // re pairs (cols 2q,2q+1) with uu; im pairs (cols 18+2q..) with vv
            acc[q]     = ffma2(tv.x == tv.x ? tv.x : tv.x, uu, acc[q]);
            acc[9 + q] = ffma2(tv.y, vv, acc[9 + q]);
        }
    }
    // NOTE on pairing above: t2[q] = (u64 cols 4q..4q+1?, ...) -- see remap:
    // Actually remap cleanly below is required; the loop above pairs
    // t2[q].x = cols (4q,4q+1) which is wrong for q>=5. Redone correctly:
    // (kept structure minimal: recompute with scalar-safe indexing)
    // -- The loop above is replaced by the corrected one here --

    // Correct accumulation (overwrites the above):
#pragma unroll
    for (int q = 0; q < 18; q++) acc[q] = 0;
#pragma unroll 2
    for (int j = 0; j < 32; j++) {
        int w = 4 * j + p + 1;
        float a = xrow[w];
        float b = xrow[256 - w];
        u64 uu = pk(a + b, a + b);
        u64 vv = pk(a - b, a - b);
        const u64* tu = reinterpret_cast<const u64*>(TK + w * 36);
#pragma unroll
        for (int q = 0; q < 9; q++) acc[q] = ffma2(tu[q], uu, acc[q]);
#pragma unroll
        for (int q = 9; q < 18; q++) acc[q] = ffma2(tu[q], vv, acc[q]);
    }

    if (p == 0) {
        float x0 = xrow[0], x128 = xrow[128];
        float ea = x0 - x128, eb = x0 + x128;
        u64 eab = pk(ea, eb), one2 = pk(1.f, 1.f);
#pragma unroll
        for (int q = 0; q < 8; q++) acc[q] = ffma2(one2, eab, acc[q]);
        acc[8] = ffma2(one2, pk(ea, 0.f), acc[8]);
    }
    __syncthreads();

    // 4-way reduction via smem (reuse Xs region), stride 37 (conflict-free)
    float* red = Xs;
    {
        float* my = red + threadIdx.x * 37;
#pragma unroll
        for (int q = 0; q < 18; q++) {
            float2 v = upk(acc[q]);
            my[2 * q] = v.x; my[2 * q + 1] = v.y;
        }
    }
    __syncthreads();

    float* ao = g_Aw + (size_t)blockIdx.x * 64 * NCA;
    for (int idx = threadIdx.x; idx < 64 * NCA; idx += 256) {
        int rr = idx / NCA, c = idx % NCA;
        const float* s = red + (rr * 4) * 37 + c;
        ao[idx] = s[0] + s[37] + s[74] + s[111];
    }
}

// ---------------------------------------------------------------------------
// K2: forward h-DFT, block per image. Thread = (kx = t&31, chunk = t>>5).
// Aw rows staged (stride 36) and read as broadcast LDS.128 -> 18 u64 pairs.
// Eh[h][kx] conflict-free. acc: 9 re + 9 im f32x2 pairs over ky.
// 8-way chunk reduction, output XfT[f][img].
// ---------------------------------------------------------------------------
__global__ void __launch_bounds__(256) k2_hdft() {
    extern __shared__ __align__(16) float sm2[];
    float2* Ehs = reinterpret_cast<float2*>(sm2);   // 256*32 float2 = 64KB
    float*  Aws = sm2 + 2 * 256 * 32;               // union: 256*36 / red 256*37

    int img = blockIdx.x;
    {
        const float4* src = reinterpret_cast<const float4*>(
            g_Aw + (size_t)img * 256 * NCA);
        float4* dst = reinterpret_cast<float4*>(Aws);
#pragma unroll
        for (int k = 0; k < 9; k++) dst[k * 256 + threadIdx.x] = src[k * 256 + threadIdx.x];
        const float4* es = reinterpret_cast<const float4*>(g_Eh);
        float4* ed = reinterpret_cast<float4*>(Ehs);
#pragma unroll
        for (int k = 0; k < 16; k++) ed[k * 256 + threadIdx.x] = es[k * 256 + threadIdx.x];
    }
    __syncthreads();

    int kx = threadIdx.x & 31, chunk = threadIdx.x >> 5;
    int h0 = chunk * 32;

    u64 accRe[9], accIm[9];
#pragma unroll
    for (int q = 0; q < 9; q++) { accRe[q] = 0; accIm[q] = 0; }

#pragma unroll 4
    for (int hh = 0; hh < 32; hh++) {
        int h = h0 + hh;
        float2 E = Ehs[h * 32 + kx];
        u64 Ex2  = pk(E.x, E.x);
        u64 Ey2  = pk(E.y, E.y);
        u64 Eyn2 = pk(-E.y, -E.y);
        const u64* c2 = reinterpret_cast<const u64*>(Aws + h * 36);
#pragma unroll
        for (int q = 0; q < 9; q++) {
            u64 cr = c2[q], ci = c2[9 + q];
            accRe[q] = ffma2(cr, Ex2, accRe[q]);
            accRe[q] = ffma2(ci, Ey2, accRe[q]);
            accIm[q] = ffma2(ci, Ex2, accIm[q]);
            accIm[q] = ffma2(cr, Eyn2, accIm[q]);
        }
    }
    __syncthreads();

    float* red = Aws;   // 256*37 floats (fits: region sized below)
    {
        float* my = red + threadIdx.x * 37;
#pragma unroll
        for (int q = 0; q < 9; q++) {
            float2 a = upk(accRe[q]);
            my[2 * q] = a.x; my[2 * q + 1] = a.y;
            float2 b = upk(accIm[q]);
            my[18 + 2 * q] = b.x; my[19 + 2 * q] = b.y;
        }
    }
    __syncthreads();

    const float sc = 1.f / 256.f;
    for (int pp = threadIdx.x; pp < F; pp += 256) {
        int kxo = pp / 17, ky = pp % 17;
        float re = 0.f, im = 0.f;
#pragma unroll
        for (int ch = 0; ch < 8; ch++) {
            const float* s = red + (ch * 32 + kxo) * 37;
            re += s[ky];
            im += s[18 + ky];
        }
        g_XfT[(size_t)pp * IMG + img] = make_float2(re * sc, im * sc);
    }
}

// ---------------------------------------------------------------------------
// K2b: weight transpose -> WT[f][i*64 + co] (co = hd*16 + o).
// ---------------------------------------------------------------------------
__global__ void __launch_bounds__(256) k2b_wt(const float* __restrict__ wr,
                                             const float* __restrict__ wi) {
    __shared__ float2 sm[16 * 65];
    int i  = blockIdx.x / 34;
    int f0 = (blockIdx.x % 34) * 16;

    for (int idx = threadIdx.x; idx < 1024; idx += 256) {
        int hdo = idx >> 4, fo = idx & 15;
        int hd = hdo >> 4, o = hdo & 15;
        size_t src = (size_t)(((hd * 64 + i) * 16) + o) * F + f0 + fo;
        sm[fo * 65 + hdo] = make_float2(wr[src], wi[src]);
    }
    __syncthreads();
    for (int idx = threadIdx.x; idx < 1024; idx += 256) {
        int fo = idx >> 6, j = idx & 63;
        g_WT[(size_t)(f0 + fo) * 4096 + i * 64 + j] = sm[fo * 65 + j];
    }
}

// ---------------------------------------------------------------------------
// K3: per-frequency complex channel mix, fully coalesced.
// ---------------------------------------------------------------------------
__global__ void __launch_bounds__(128) k3_mix() {
    __shared__ __align__(16) float2 Xs[512];
    __shared__ __align__(16) float2 Ws[4096];
    int f = blockIdx.x;

    const float4* wsrc = reinterpret_cast<const float4*>(g_WT + (size_t)f * 4096);
    float4* wd = reinterpret_cast<float4*>(Ws);
    for (int t = threadIdx.x; t < 2048; t += 128) wd[t] = wsrc[t];
    const float4* xsrc = reinterpret_cast<const float4*>(g_XfT + (size_t)f * IMG);
    float4* xd = reinterpret_cast<float4*>(Xs);
    for (int t = threadIdx.x; t < 256; t += 128) xd[t] = xsrc[t];
    __syncthreads();

#pragma unroll
    for (int u = 0; u < 4; u++) {
        int t2 = threadIdx.x + u * 128;
        int b = t2 >> 6, co = t2 & 63;
        float yr = 0.f, yi = 0.f;
#pragma unroll 8
        for (int i = 0; i < 64; i++) {
            float2 X = Xs[b * 64 + i];
            float2 W = Ws[i * 64 + co];
            yr += X.x * W.x - X.y * W.y;
            yi += X.x * W.y + X.y * W.x;
        }
        g_YfT[(size_t)f * IMG + t2] = make_float2(yr, yi);
    }
}

// ---------------------------------------------------------------------------
// K45: fused inverse h-DFT + folded w-synthesis. Block per image.
// Phase A: thread per h, ky-paired f32x2, writes G to smem Gp[col][h]
// (col: re ky at ky, im ky at 18+ky) -- conflict-free column stores,
// adjacent-h float2 reads give phase B its packed row-pairs for free.
// Phase B: thread (w = t&127, half); ce/cs tables in regs; E +- O folding;
// w==0 lanes also emit column 128. Coalesced stores.
// ---------------------------------------------------------------------------
__global__ void __launch_bounds__(256) k45_fused(const float* __restrict__ bias,
                                                float* __restrict__ out) {
    extern __shared__ __align__(16) float sm4[];
    float2* EhTs = reinterpret_cast<float2*>(sm4);        // 32*256 = 64KB
    float*  Ysr  = sm4 + 2 * 32 * 256;                    // 32*24
    float*  Ysi  = Ysr + 32 * 24;                         // 32*24
    float*  Gp   = Ysi + 32 * 24;                         // 36*256

    int img = blockIdx.x;
    {
        const float4* es = reinterpret_cast<const float4*>(g_EhT);
        float4* ed = reinterpret_cast<float4*>(EhTs);
#pragma unroll
        for (int k = 0; k < 16; k++) ed[k * 256 + threadIdx.x] = es[k * 256 + threadIdx.x];
        for (int i = threadIdx.x; i < 32 * 24; i += 256) { Ysr[i] = 0.f; Ysi[i] = 0.f; }
    }
    __syncthreads();
    for (int i = threadIdx.x; i < F; i += 256) {
        float2 y = g_YfT[(size_t)i * IMG + img];
        int kx = i / 17, ky = i % 17;
        Ysr[kx * 24 + ky] = y.x;
        Ysi[kx * 24 + ky] = y.y;
    }
    __syncthreads();

    // ---- Phase A ----
    {
        int h = threadIdx.x;
        u64 grp[9], gip[9];
#pragma unroll
        for (int q = 0; q < 9; q++) { grp[q] = 0; gip[q] = 0; }

#pragma unroll 4
        for (int kx = 0; kx < 32; kx++) {
            float2 E = EhTs[kx * 256 + h];
            u64 Ex2  = pk(E.x, E.x);
            u64 Ey2  = pk(E.y, E.y);
            u64 Eyn2 = pk(-E.y, -E.y);
            const u64* yr = reinterpret_cast<const u64*>(Ysr + kx * 24);
            const u64* yi = reinterpret_cast<const u64*>(Ysi + kx * 24);
#pragma unroll
            for (int q = 0; q < 9; q++) {
                u64 Yr = yr[q], Yi = yi[q];
                grp[q] = ffma2(Yr, Ex2, grp[q]);
                grp[q] = ffma2(Yi, Eyn2, grp[q]);
                gip[q] = ffma2(Yr, Ey2, gip[q]);
                gip[q] = ffma2(Yi, Ex2, gip[q]);
            }
        }
#pragma unroll
        for (int q = 0; q < 9; q++) {
            float2 a = upk(grp[q]);
            Gp[(2 * q) * 256 + h]     = a.x;
            Gp[(2 * q + 1) * 256 + h] = a.y;
            float2 b = upk(gip[q]);
            Gp[(18 + 2 * q) * 256 + h] = b.x;
            Gp[(19 + 2 * q) * 256 + h] = b.y;
        }
    }
    __syncthreads();

    // ---- Phase B ----
    int w = threadIdx.x & 127, half = threadIdx.x >> 7;
    u64 ce2[17], cs2[17];
    const u64* PC = reinterpret_cast<const u64*>(g_PC5);
    const u64* PS = reinterpret_cast<const u64*>(g_PS5);
#pragma unroll
    for (int k = 0; k < 17; k++) {
        ce2[k] = PC[k * 128 + w];
        cs2[k] = PS[k * 128 + w];
    }
    float bv = bias[img & 63];
    u64 m0 = pk(1.f / 256.f, 1.f / 256.f);
    u64 mp = pk(2.f / 256.f, 2.f / 256.f);
    u64 mn = pk(-2.f / 256.f, -2.f / 256.f);
    float* ob = out + (size_t)img * 65536;

#pragma unroll 2
    for (int q = 0; q < 64; q++) {
        int pp = half * 64 + q;          // rows 2pp, 2pp+1
        u64 Ea = 0, Oa = 0;
        u64 gre[17];
#pragma unroll
        for (int k = 0; k < 17; k++) {
            gre[k] = *reinterpret_cast<const u64*>(Gp + k * 256 + 2 * pp);
            Ea = ffma2(gre[k], ce2[k], Ea);
        }
#pragma unroll
        for (int k = 1; k < 17; k++) {
            u64 gim = *reinterpret_cast<const u64*>(Gp + (18 + k) * 256 + 2 * pp);
            Oa = ffma2(gim, cs2[k], Oa);
        }
        float2 e = upk(Ea), o = upk(Oa);
        float* r0 = ob + (size_t)(2 * pp) * 256;
        r0[w]        = e.x + o.x + bv;
        r0[256 + w]  = e.y + o.y + bv;
        if (w) {
            int wm = 256 - w;
            r0[wm]       = e.x - o.x + bv;
            r0[256 + wm] = e.y - o.y + bv;
        } else {
            u64 E8 = ffma2(gre[0], m0, (u64)0);
#pragma unroll
            for (int k = 1; k < 17; k++) E8 = ffma2(gre[k], (k & 1) ? mn : mp, E8);
            float2 a8 = upk(E8);
            r0[128]       = a8.x + bv;
            r0[256 + 128] = a8.y + bv;
        }
    }
}

// ---------------------------------------------------------------------------
extern "C" void kernel_launch(void* const* d_in, const int* in_sizes, int n_in,
                              void* d_out, int out_size) {
    const float* x    = (const float*)d_in[0];
    const float* wr   = (const float*)d_in[1];
    const float* wi   = (const float*)d_in[2];
    const float* bias = (const float*)d_in[3];
    float* out = (float*)d_out;

    const int K1_SMEM = (4656 + 64 * 260) * 4;            // 85184 B
    const int K2_SMEM = (2 * 256 * 32 + 256 * 37) * 4;    // 103424 B
    const int K45_SMEM = (2 * 32 * 256 + 2 * 32 * 24 + 36 * 256) * 4; // 108544 B
    cudaFuncSetAttribute(k1_wdft, cudaFuncAttributeMaxDynamicSharedMemorySize, K1_SMEM);
    cudaFuncSetAttribute(k2_hdft, cudaFuncAttributeMaxDynamicSharedMemorySize, K2_SMEM);
    cudaFuncSetAttribute(k45_fused, cudaFuncAttributeMaxDynamicSharedMemorySize, K45_SMEM);

    k0_tables<<<64, 256>>>();
    k1_wdft<<<2048, 256, K1_SMEM>>>(x);
    k2_hdft<<<IMG, 256, K2_SMEM>>>();
    k2b_wt<<<64 * 34, 256>>>(wr, wi);
    k3_mix<<<F, 128>>>();
    k45_fused<<<IMG, 256, K45_SMEM>>>(bias, out);
}

// round 7
// speedup vs baseline: 1.6230x; 1.0169x over previous
#include <cuda_runtime.h>
#include <math.h>

// MHFSpectralConv2D via pruned-DFT factorization, round 7.
// = round-5/6 source + the missing __syncthreads() in k12 between the fold
// reads of Xs and the reduction writes to red (which aliases Xs).
// k12: fused (folded w-DFT -> smem Aw -> h-DFT) per image -> XfT[f][img]
// k2b: weight transpose (contiguous reads)  k3: per-freq complex mix
// k45: fused inverse h-DFT + folded f32x2 w-synthesis.

namespace {
constexpr int IMG = 512;                      // B*C = 8*64
constexpr int MX = 32, MY = 17, F = MX * MY;  // 544 live freqs
constexpr int XSS = 264;                      // k12 x-stage row stride
}

// ---- persistent device scratch / tables ----
__device__ float  g_TK1[129 * 36];   // [w][36]: cos ky 0..16 | 0 | -sin | 0
__device__ float2 g_Eh[256 * 32];    // [h][kx] = (cos, sin)
__device__ float2 g_EhT[32 * 256];   // [kx][h]
__device__ float2 g_PC5[17 * 128];   // K5 cos coef, duplicated lanes
__device__ float2 g_PS5[17 * 128];   // K5 sin coef, duplicated lanes
__device__ float2 g_XfT[(size_t)F * IMG];     // [f][img]
__device__ float2 g_WT[(size_t)F * 4096];     // [f][i*64+co]
__device__ float2 g_YfT[(size_t)F * IMG];     // [f][img]

// ---- f32x2 helpers ----
typedef unsigned long long u64;
__device__ __forceinline__ u64 ffma2(u64 a, u64 b, u64 c) {
    u64 d;
    asm("fma.rn.f32x2 %0, %1, %2, %3;" : "=l"(d) : "l"(a), "l"(b), "l"(c));
    return d;
}
__device__ __forceinline__ float2 upk(u64 v) {
    float2 r;
    asm("mov.b64 {%0,%1}, %2;" : "=f"(r.x), "=f"(r.y) : "l"(v));
    return r;
}
__device__ __forceinline__ u64 pk(float a, float b) {
    u64 v;
    asm("mov.b64 %0, {%1,%2};" : "=l"(v) : "f"(a), "f"(b));
    return v;
}

// ---------------------------------------------------------------------------
// K0a/K0b: trig tables (exact integer mod-256 reduction).
// ---------------------------------------------------------------------------
__global__ void k0a_tables() {
    int tid = blockIdx.x * blockDim.x + threadIdx.x;
    int nt  = blockDim.x * gridDim.x;
    for (int idx = tid; idx < 129 * 36; idx += nt) {
        int w = idx / 36, c = idx % 36;
        float v = 0.f;
        if (c < 17) {
            int m = (c * w) & 255; float s, co;
            sincospif((float)m * (1.f / 128.f), &s, &co);
            v = co;
        } else if (c >= 18 && c < 35) {
            int ky = c - 18;
            int m = (ky * w) & 255; float s, co;
            sincospif((float)m * (1.f / 128.f), &s, &co);
            v = -s;
        }
        g_TK1[idx] = v;
    }
    for (int idx = tid; idx < 256 * 32; idx += nt) {
        int h = idx >> 5, kx = idx & 31;
        int m = (kx * h) & 255; float s, co;
        sincospif((float)m * (1.f / 128.f), &s, &co);
        g_Eh[idx] = make_float2(co, s);
        g_EhT[kx * 256 + h] = make_float2(co, s);
    }
}
__global__ void k0b_tables() {
    int tid = blockIdx.x * blockDim.x + threadIdx.x;
    int nt  = blockDim.x * gridDim.x;
    for (int idx = tid; idx < 17 * 128; idx += nt) {
        int k = idx >> 7, w = idx & 127;
        int m = (k * w) & 255; float s, co;
        sincospif((float)m * (1.f / 128.f), &s, &co);
        float ce = (k == 0) ? (1.f / 256.f) : co * (2.f / 256.f);
        float cs = -s * (2.f / 256.f);
        g_PC5[idx] = make_float2(ce, ce);
        g_PS5[idx] = make_float2(cs, cs);
    }
}

// ---------------------------------------------------------------------------
// K2b: weight transpose -> WT[f][i*64 + co] (co = hd*16 + o).
// Block per (hd, i): reads are two fully contiguous 34.8KB streams;
// smem stride 545 (odd) -> conflict-free column gathers; writes are
// 128B-per-f coalesced float2 stores.
// ---------------------------------------------------------------------------
__global__ void __launch_bounds__(256) k2b_wt(const float* __restrict__ wr,
                                             const float* __restrict__ wi) {
    extern __shared__ float smw[];
    float* smr = smw;            // 16*545
    float* smi = smw + 16 * 545; // 16*545

    int hd = blockIdx.x >> 6, i = blockIdx.x & 63;
    size_t base = (size_t)((hd * 64 + i) * 16) * F;   // 16 rows x 544

    const float4* wr4 = reinterpret_cast<const float4*>(wr + base);
    const float4* wi4 = reinterpret_cast<const float4*>(wi + base);
    for (int idx = threadIdx.x; idx < 2176; idx += 256) {
        int o = (idx * 4) / 544, fb = (idx * 4) % 544;
        float4 a = wr4[idx];
        float4 b = wi4[idx];
        float* dr = smr + o * 545 + fb;
        float* di = smi + o * 545 + fb;
        dr[0] = a.x; dr[1] = a.y; dr[2] = a.z; dr[3] = a.w;
        di[0] = b.x; di[1] = b.y; di[2] = b.z; di[3] = b.w;
    }
    __syncthreads();

    int cobase = i * 64 + hd * 16;
    for (int idx = threadIdx.x; idx < 8704; idx += 256) {
        int f = idx >> 4, o = idx & 15;
        g_WT[(size_t)f * 4096 + cobase + o] =
            make_float2(smr[o * 545 + f], smi[o * 545 + f]);
    }
}

// ---------------------------------------------------------------------------
// K12: fused forward transform, block per image (512 blocks, 256 threads).
// Phase 1 (x8 chunks of 32 rows): folded w-DFT. Thread (r=t>>3, p=t&7)
// handles w = 8j+p+1; Xs stride 264 -> banks 8r±p all distinct.
// Reduce 8 partials: 2 bfly-shuffle rounds -> 2 partials -> smem (aliased
// in Xs; WRITES BARRIER-SEPARATED FROM FOLD READS) -> Aw[row][36] in smem.
// Phase 2: h-DFT from smem Aw (broadcast u64 reads) + __ldg Eh;
// 8-chunk reduction via smem (aliased over TK+Xs); writes XfT[f][img].
// ---------------------------------------------------------------------------
__global__ void __launch_bounds__(256) k12_fwd(const float* __restrict__ x) {
    extern __shared__ __align__(16) float sm[];
    float* U  = sm;              // 13104 floats: TK[0..4655] | Xs/red
    float* TK = U;
    float* Xs = U + 4656;        // 32*264 = 8448 (red aliases here)
    float* Aw = U + 13104;       // 256*36 = 9216

    int t = threadIdx.x;
    int img = blockIdx.x;

    for (int i = t; i < 129 * 36; i += 256) TK[i] = g_TK1[i];

    int r = t >> 3, p = t & 7;
    float* red = Xs;             // 32 rows * 2 parts * 37

    for (int chunk = 0; chunk < 8; chunk++) {
        __syncthreads();   // red/Xs readers done; TK ready (chunk 0)
        const float4* xg = reinterpret_cast<const float4*>(
            x + (size_t)img * 65536 + chunk * 8192);
#pragma unroll
        for (int k = 0; k < 8; k++) {
            int fidx = k * 256 + t;
            int row = fidx >> 6, c4 = fidx & 63;
            *reinterpret_cast<float4*>(Xs + row * XSS + c4 * 4) = xg[fidx];
        }
        __syncthreads();

        const float* xrow = Xs + r * XSS;
        u64 acc[18];
#pragma unroll
        for (int q = 0; q < 18; q++) acc[q] = 0;

#pragma unroll 2
        for (int j = 0; j < 16; j++) {
            int w = 8 * j + p + 1;
            float a = xrow[w];
            float b = xrow[256 - w];
            u64 uu = pk(a + b, a + b);
            u64 vv = pk(a - b, a - b);
            const u64* tu = reinterpret_cast<const u64*>(TK + w * 36);
#pragma unroll
            for (int q = 0; q < 9; q++) acc[q] = ffma2(tu[q], uu, acc[q]);
#pragma unroll
            for (int q = 9; q < 18; q++) acc[q] = ffma2(tu[q], vv, acc[q]);
        }
        if (p == 0) {
            float x0 = xrow[0], x128 = xrow[128];
            float ea = x0 - x128, eb = x0 + x128;
            u64 eab = pk(ea, eb), one2 = pk(1.f, 1.f);
#pragma unroll
            for (int q = 0; q < 8; q++) acc[q] = ffma2(one2, eab, acc[q]);
            acc[8] = ffma2(one2, pk(ea, 0.f), acc[8]);
        }

        // All warps must finish reading Xs before red (aliased) is written.
        __syncthreads();

        // 2-round bfly over p (xor 1, 2); lanes p==0 / p==4 hold 2 partials
        bool wrt = (p == 0) | (p == 4);
        int rbase = (r * 2 + (p >> 2)) * 37;
#pragma unroll
        for (int q = 0; q < 18; q++) {
            float2 v = upk(acc[q]);
            v.x += __shfl_xor_sync(0xffffffffu, v.x, 1);
            v.y += __shfl_xor_sync(0xffffffffu, v.y, 1);
            v.x += __shfl_xor_sync(0xffffffffu, v.x, 2);
            v.y += __shfl_xor_sync(0xffffffffu, v.y, 2);
            if (wrt) {
                red[rbase + 2 * q]     = v.x;
                red[rbase + 2 * q + 1] = v.y;
            }
        }
        __syncthreads();

        for (int idx = t; idx < 32 * 36; idx += 256) {
            int row = idx / 36, c = idx % 36;
            Aw[(chunk * 32 + row) * 36 + c] =
                red[(row * 2) * 37 + c] + red[(row * 2 + 1) * 37 + c];
        }
    }
    __syncthreads();

    // ---- Phase 2: h-DFT ----
    int kx = t & 31, ch = t >> 5;
    int h0 = ch * 32;
    u64 accRe[9], accIm[9];
#pragma unroll
    for (int q = 0; q < 9; q++) { accRe[q] = 0; accIm[q] = 0; }

#pragma unroll 4
    for (int hh = 0; hh < 32; hh++) {
        int h = h0 + hh;
        float2 E = __ldg(&g_Eh[h * 32 + kx]);
        u64 Ex2  = pk(E.x, E.x);
        u64 Ey2  = pk(E.y, E.y);
        u64 Eyn2 = pk(-E.y, -E.y);
        const u64* c2 = reinterpret_cast<const u64*>(Aw + h * 36);
#pragma unroll
        for (int q = 0; q < 9; q++) {
            u64 cr = c2[q], ci = c2[9 + q];
            accRe[q] = ffma2(cr, Ex2, accRe[q]);
            accRe[q] = ffma2(ci, Ey2, accRe[q]);
            accIm[q] = ffma2(ci, Ex2, accIm[q]);
            accIm[q] = ffma2(cr, Eyn2, accIm[q]);
        }
    }
    __syncthreads();

    float* red2 = U;   // 256*37 = 9472 <= 13104
    {
        float* my = red2 + t * 37;
#pragma unroll
        for (int q = 0; q < 9; q++) {
            float2 a = upk(accRe[q]);
            my[2 * q] = a.x; my[2 * q + 1] = a.y;
            float2 b = upk(accIm[q]);
            my[18 + 2 * q] = b.x; my[19 + 2 * q] = b.y;
        }
    }
    __syncthreads();

    const float sc = 1.f / 256.f;
    for (int pp = t; pp < F; pp += 256) {
        int kxo = pp / 17, ky = pp % 17;
        float re = 0.f, im = 0.f;
#pragma unroll
        for (int c = 0; c < 8; c++) {
            const float* s = red2 + (c * 32 + kxo) * 37;
            re += s[ky];
            im += s[18 + ky];
        }
        g_XfT[(size_t)pp * IMG + img] = make_float2(re * sc, im * sc);
    }
}

// ---------------------------------------------------------------------------
// K3: per-frequency complex channel mix, fully coalesced, 256 threads.
// ---------------------------------------------------------------------------
__global__ void __launch_bounds__(256) k3_mix() {
    __shared__ __align__(16) float2 Xs[512];
    __shared__ __align__(16) float2 Ws[4096];
    int f = blockIdx.x;

    const float4* wsrc = reinterpret_cast<const float4*>(g_WT + (size_t)f * 4096);
    float4* wd = reinterpret_cast<float4*>(Ws);
    for (int t = threadIdx.x; t < 2048; t += 256) wd[t] = wsrc[t];
    const float4* xsrc = reinterpret_cast<const float4*>(g_XfT + (size_t)f * IMG);
    float4* xd = reinterpret_cast<float4*>(Xs);
    if (threadIdx.x < 256) xd[threadIdx.x] = xsrc[threadIdx.x];
    __syncthreads();

#pragma unroll
    for (int u = 0; u < 2; u++) {
        int t2 = threadIdx.x + u * 256;
        int b = t2 >> 6, co = t2 & 63;
        float yr = 0.f, yi = 0.f;
#pragma unroll 8
        for (int i = 0; i < 64; i++) {
            float2 X = Xs[b * 64 + i];
            float2 W = Ws[i * 64 + co];
            yr += X.x * W.x - X.y * W.y;
            yi += X.x * W.y + X.y * W.x;
        }
        g_YfT[(size_t)f * IMG + t2] = make_float2(yr, yi);
    }
}

// ---------------------------------------------------------------------------
// K45: fused inverse h-DFT + folded w-synthesis. Block per image.
// ---------------------------------------------------------------------------
__global__ void __launch_bounds__(256) k45_fused(const float* __restrict__ bias,
                                                float* __restrict__ out) {
    extern __shared__ __align__(16) float sm4[];
    float2* EhTs = reinterpret_cast<float2*>(sm4);        // 32*256 = 64KB
    float*  Ysr  = sm4 + 2 * 32 * 256;                    // 32*24
    float*  Ysi  = Ysr + 32 * 24;                         // 32*24
    float*  Gp   = Ysi + 32 * 24;                         // 36*256

    int img = blockIdx.x;
    {
        const float4* es = reinterpret_cast<const float4*>(g_EhT);
        float4* ed = reinterpret_cast<float4*>(EhTs);
#pragma unroll
        for (int k = 0; k < 16; k++) ed[k * 256 + threadIdx.x] = es[k * 256 + threadIdx.x];
        for (int i = threadIdx.x; i < 32 * 24; i += 256) { Ysr[i] = 0.f; Ysi[i] = 0.f; }
    }
    __syncthreads();
    for (int i = threadIdx.x; i < F; i += 256) {
        float2 y = g_YfT[(size_t)i * IMG + img];
        int kx = i / 17, ky = i % 17;
        Ysr[kx * 24 + ky] = y.x;
        Ysi[kx * 24 + ky] = y.y;
    }
    __syncthreads();

    // ---- Phase A: inverse h-DFT -> Gp[col][h] ----
    {
        int h = threadIdx.x;
        u64 grp[9], gip[9];
#pragma unroll
        for (int q = 0; q < 9; q++) { grp[q] = 0; gip[q] = 0; }

#pragma unroll 4
        for (int kx = 0; kx < 32; kx++) {
            float2 E = EhTs[kx * 256 + h];
            u64 Ex2  = pk(E.x, E.x);
            u64 Ey2  = pk(E.y, E.y);
            u64 Eyn2 = pk(-E.y, -E.y);
            const u64* yr = reinterpret_cast<const u64*>(Ysr + kx * 24);
            const u64* yi = reinterpret_cast<const u64*>(Ysi + kx * 24);
#pragma unroll
            for (int q = 0; q < 9; q++) {
                u64 Yr = yr[q], Yi = yi[q];
                grp[q] = ffma2(Yr, Ex2, grp[q]);
                grp[q] = ffma2(Yi, Eyn2, grp[q]);
                gip[q] = ffma2(Yr, Ey2, gip[q]);
                gip[q] = ffma2(Yi, Ex2, gip[q]);
            }
        }
#pragma unroll
        for (int q = 0; q < 9; q++) {
            float2 a = upk(grp[q]);
            Gp[(2 * q) * 256 + h]     = a.x;
            Gp[(2 * q + 1) * 256 + h] = a.y;
            float2 b = upk(gip[q]);
            Gp[(18 + 2 * q) * 256 + h] = b.x;
            Gp[(19 + 2 * q) * 256 + h] = b.y;
        }
    }
    __syncthreads();

    // ---- Phase B: folded w-synthesis ----
    int w = threadIdx.x & 127, half = threadIdx.x >> 7;
    u64 ce2[17], cs2[17];
    const u64* PC = reinterpret_cast<const u64*>(g_PC5);
    const u64* PS = reinterpret_cast<const u64*>(g_PS5);
#pragma unroll
    for (int k = 0; k < 17; k++) {
        ce2[k] = PC[k * 128 + w];
        cs2[k] = PS[k * 128 + w];
    }
    float bv = bias[img & 63];
    u64 m0 = pk(1.f / 256.f, 1.f / 256.f);
    u64 mp = pk(2.f / 256.f, 2.f / 256.f);
    u64 mn = pk(-2.f / 256.f, -2.f / 256.f);
    float* ob = out + (size_t)img * 65536;

#pragma unroll 2
    for (int q = 0; q < 64; q++) {
        int pp = half * 64 + q;
        u64 Ea = 0, Oa = 0;
        u64 gre[17];
#pragma unroll
        for (int k = 0; k < 17; k++) {
            gre[k] = *reinterpret_cast<const u64*>(Gp + k * 256 + 2 * pp);
            Ea = ffma2(gre[k], ce2[k], Ea);
        }
#pragma unroll
        for (int k = 1; k < 17; k++) {
            u64 gim = *reinterpret_cast<const u64*>(Gp + (18 + k) * 256 + 2 * pp);
            Oa = ffma2(gim, cs2[k], Oa);
        }
        float2 e = upk(Ea), o = upk(Oa);
        float* r0 = ob + (size_t)(2 * pp) * 256;
        r0[w]        = e.x + o.x + bv;
        r0[256 + w]  = e.y + o.y + bv;
        if (w) {
            int wm = 256 - w;
            r0[wm]       = e.x - o.x + bv;
            r0[256 + wm] = e.y - o.y + bv;
        } else {
            u64 E8 = ffma2(gre[0], m0, (u64)0);
#pragma unroll
            for (int k = 1; k < 17; k++) E8 = ffma2(gre[k], (k & 1) ? mn : mp, E8);
            float2 a8 = upk(E8);
            r0[128]       = a8.x + bv;
            r0[256 + 128] = a8.y + bv;
        }
    }
}

// ---------------------------------------------------------------------------
extern "C" void kernel_launch(void* const* d_in, const int* in_sizes, int n_in,
                              void* d_out, int out_size) {
    const float* x    = (const float*)d_in[0];
    const float* wr   = (const float*)d_in[1];
    const float* wi   = (const float*)d_in[2];
    const float* bias = (const float*)d_in[3];
    float* out = (float*)d_out;

    const int K2B_SMEM = 2 * 16 * 545 * 4;                            // 69760 B
    const int K12_SMEM = (4656 + 8448 + 9216) * 4;                    // 89280 B
    const int K45_SMEM = (2 * 32 * 256 + 2 * 32 * 24 + 36 * 256) * 4; // 108544 B
    cudaFuncSetAttribute(k2b_wt, cudaFuncAttributeMaxDynamicSharedMemorySize, K2B_SMEM);
    cudaFuncSetAttribute(k12_fwd, cudaFuncAttributeMaxDynamicSharedMemorySize, K12_SMEM);
    cudaFuncSetAttribute(k45_fused, cudaFuncAttributeMaxDynamicSharedMemorySize, K45_SMEM);

    k0a_tables<<<64, 256>>>();
    k0b_tables<<<16, 256>>>();
    k2b_wt<<<256, 256, K2B_SMEM>>>(wr, wi);
    k12_fwd<<<IMG, 256, K12_SMEM>>>(x);      // captured launch (index 3)
    k3_mix<<<F, 256>>>();
    k45_fused<<<IMG, 256, K45_SMEM>>>(bias, out);
}